// round 2
// baseline (speedup 1.0000x reference)
#include <cuda_runtime.h>
#include <cstdint>

#define D_ 256
#define L_ 4
#define H_ 8
#define TM 32
#define NT 256

// ---------------- packed f32x2 helpers (sm_103a) ----------------
__device__ __forceinline__ unsigned long long fma2(unsigned long long a,
                                                   unsigned long long b,
                                                   unsigned long long c) {
    unsigned long long r;
    asm("fma.rn.f32x2 %0, %1, %2, %3;" : "=l"(r) : "l"(a), "l"(b), "l"(c));
    return r;
}
__device__ __forceinline__ float f2sum(unsigned long long v) {
    float lo, hi;
    asm("mov.b64 {%0,%1}, %2;" : "=f"(lo), "=f"(hi) : "l"(v));
    return lo + hi;
}

__device__ __forceinline__ float wred(float v) {
#pragma unroll
    for (int s = 16; s > 0; s >>= 1) v += __shfl_xor_sync(0xffffffffu, v, s);
    return v;
}

// acc[m] = sum_i sA[m*RS + i] * Wrow[i], i in [0,256)
// A in smem (warp-broadcast LDS.128), W streamed from global (L2-hot),
// double-buffered, f32x2 packed FMAs.
template <int RS>
__device__ __forceinline__ void gemv(const float* __restrict__ sA,
                                     const float* __restrict__ Wrow,
                                     float* __restrict__ acc) {
    unsigned long long a2[TM];
#pragma unroll
    for (int m = 0; m < TM; m++) a2[m] = 0ull;
    const ulonglong2* W2 = reinterpret_cast<const ulonglong2*>(Wrow);
    ulonglong2 w = __ldg(W2);
#pragma unroll 1
    for (int ic = 0; ic < D_ / 4; ic++) {
        ulonglong2 wn = __ldg(W2 + ((ic + 1) & (D_ / 4 - 1)));
        const char* ap = reinterpret_cast<const char*>(sA) + ic * 16;
#pragma unroll
        for (int m = 0; m < TM; m++) {
            ulonglong2 a = *reinterpret_cast<const ulonglong2*>(ap + m * (RS * 4));
            a2[m] = fma2(w.x, a.x, a2[m]);
            a2[m] = fma2(w.y, a.y, a2[m]);
        }
        w = wn;
    }
#pragma unroll
    for (int m = 0; m < TM; m++) acc[m] = f2sum(a2[m]);
}

__device__ __forceinline__ void layernorm_inplace(float* sX, const float* __restrict__ g,
                                                  const float* __restrict__ b,
                                                  float* smu, float* srstd) {
    const int w = threadIdx.x >> 5, lane = threadIdx.x & 31;
#pragma unroll
    for (int k = 0; k < TM / 8; k++) {
        int m = w * (TM / 8) + k;
        float s = 0.f, s2 = 0.f;
#pragma unroll
        for (int i = lane; i < D_; i += 32) {
            float v = sX[m * D_ + i];
            s += v;
            s2 += v * v;
        }
        s = wred(s);
        s2 = wred(s2);
        if (lane == 0) {
            float mu = s * (1.f / D_);
            float var = s2 * (1.f / D_) - mu * mu;
            smu[m] = mu;
            srstd[m] = rsqrtf(var + 1e-5f);
        }
    }
    __syncthreads();
    const int o = threadIdx.x;
    float gg = __ldg(g + o), bb = __ldg(b + o);
#pragma unroll
    for (int m = 0; m < TM; m++)
        sX[m * D_ + o] = (sX[m * D_ + o] - smu[m]) * srstd[m] * gg + bb;
    __syncthreads();
}

constexpr int SMEM_FLOATS = TM * L_ * D_   // sM (bank)          32768
                            + TM * D_      // sE                  8192
                            + TM * D_      // sX                  8192
                            + TM * H_ * L_ // sAttn               1024
                            + TM + TM      // smu, srstd
                            + TM + TM      // sValid, sSaved
                            + TM * L_;     // sKpm
constexpr int SMEM_BYTES = SMEM_FLOATS * 4; // 201728

__global__ void __launch_bounds__(NT)
mb_kernel(const float* __restrict__ E, const float* __restrict__ scores,
          const float* __restrict__ bank, const unsigned int* __restrict__ maskw,
          const float* __restrict__ Wsave, const float* __restrict__ bsave,
          const float* __restrict__ Win, const float* __restrict__ bin,
          const float* __restrict__ Wout, const float* __restrict__ bout,
          const float* __restrict__ W1, const float* __restrict__ b1,
          const float* __restrict__ W2, const float* __restrict__ b2,
          const float* __restrict__ g1, const float* __restrict__ be1,
          const float* __restrict__ g2, const float* __restrict__ be2,
          float* __restrict__ out_emb, float* __restrict__ out_bank,
          float* __restrict__ out_mask, int N) {
    extern __shared__ float sm[];
    float* sM = sm;                      // [TM][L][D]
    float* sE = sM + TM * L_ * D_;       // [TM][D]
    float* sX = sE + TM * D_;            // [TM][D] (ctx / e1 / e2 / final)
    float* sAttn = sX + TM * D_;         // [TM][H][L]
    float* smu = sAttn + TM * H_ * L_;
    float* srstd = smu + TM;
    float* sValid = srstd + TM;
    float* sSaved = sValid + TM;
    float* sKpm = sSaved + TM;           // [TM][L]

    const int tid = threadIdx.x;
    const int o = tid;
    const long base = (long)blockIdx.x * TM;
    long nvl = (long)N - base;
    const int nval = nvl > TM ? TM : (int)(nvl > 0 ? nvl : 0);

    // ---- flags + new_mask output ----
    if (tid < TM) {
        int m = tid;
        if (m < nval) {
            long g = base + m;
            float sc = scores[g];
            float sv = (sc > 0.f) ? 1.f : 0.f;
            unsigned int mw[L_];
#pragma unroll
            for (int l = 0; l < L_; l++) mw[l] = maskw[g * L_ + l];
            float valid = (mw[L_ - 1] == 0u) ? 1.f : 0.f;
            sSaved[m] = sv;
            sValid[m] = valid;
#pragma unroll
            for (int l = 0; l < L_; l++)
                sKpm[m * L_ + l] = (valid > 0.5f && mw[l] != 0u) ? 1.f : 0.f;
#pragma unroll
            for (int l = 0; l < L_; l++) {
                float om;
                if (sv > 0.5f)
                    om = (l < L_ - 1) ? ((mw[l + 1] != 0u) ? 1.f : 0.f) : 0.f;
                else
                    om = (mw[l] != 0u) ? 1.f : 0.f;
                out_mask[g * L_ + l] = om;
            }
        } else {
            sSaved[m] = 0.f;
            sValid[m] = 0.f;
#pragma unroll
            for (int l = 0; l < L_; l++) sKpm[m * L_ + l] = 0.f;
        }
    }

    // ---- load embeddings + bank into smem (flat float4 copies) ----
    {
        const float4* src = reinterpret_cast<const float4*>(E + base * D_);
        float4* dst = reinterpret_cast<float4*>(sE);
        for (int idx = tid; idx < TM * D_ / 4; idx += NT) {
            int m = idx / (D_ / 4);
            dst[idx] = (m < nval) ? __ldg(src + idx) : make_float4(0, 0, 0, 0);
        }
        const float4* srcB = reinterpret_cast<const float4*>(bank + base * L_ * D_);
        float4* dstB = reinterpret_cast<float4*>(sM);
        for (int idx = tid; idx < TM * L_ * D_ / 4; idx += NT) {
            int m = idx / (L_ * D_ / 4);
            dstB[idx] = (m < nval) ? __ldg(srcB + idx) : make_float4(0, 0, 0, 0);
        }
    }
    __syncthreads();

    // ---- early new_bank writes (everything except the save row) ----
    {
        float4* ob = reinterpret_cast<float4*>(out_bank);
        const float4* sB = reinterpret_cast<const float4*>(sM);
        for (int idx = tid; idx < TM * L_ * D_ / 4; idx += NT) {
            int m = idx / (L_ * D_ / 4);
            if (m >= nval) continue;
            int rem = idx - m * (L_ * D_ / 4);
            int r = rem / (D_ / 4);
            bool sv = sSaved[m] > 0.5f;
            float4 v;
            if (sv) {
                if (r == L_ - 1) continue;  // written at the end (save_embed)
                v = sB[idx + (D_ / 4)];     // shift: old row r+1 -> new row r
            } else {
                v = sB[idx];
            }
            ob[(base + m) * (L_ * D_ / 4) + rem] = v;
        }
    }

    // ---- Q projection (kept in registers) ----
    float qreg[TM];
    gemv<D_>(sE, Win + (size_t)o * D_, qreg);
    {
        float bq = __ldg(bin + o);
#pragma unroll
        for (int m = 0; m < TM; m++) qreg[m] += bq;
    }

    // ---- K projection + logits (warp == head; reduce over 32 dims) ----
    const int h = tid >> 5, lane = tid & 31;
    {
        float bk = __ldg(bin + D_ + o);
        const float* Wk = Win + (size_t)(D_ + o) * D_;
        for (int l = 0; l < L_; l++) {
            float ka[TM];
            gemv<L_ * D_>(sM + l * D_, Wk, ka);
#pragma unroll
            for (int m = 0; m < TM; m++) {
                float p = (ka[m] + bk) * qreg[m];
                p = wred(p);
                if (lane == 0) sAttn[(m * H_ + h) * L_ + l] = p;
            }
        }
    }
    __syncthreads();

    // ---- masked softmax over L (one thread per (m,h)) ----
    {
        int m = tid >> 3, hh = tid & 7;
        float* lr = &sAttn[(m * H_ + hh) * L_];
        float lg[L_];
#pragma unroll
        for (int l = 0; l < L_; l++) {
            float v = lr[l] * 0.17677669529663687f;  // 1/sqrt(32)
            if (sKpm[m * L_ + l] > 0.5f) v = -1e9f;
            lg[l] = v;
        }
        float mx = fmaxf(fmaxf(lg[0], lg[1]), fmaxf(lg[2], lg[3]));
        float ssum = 0.f;
#pragma unroll
        for (int l = 0; l < L_; l++) {
            lg[l] = expf(lg[l] - mx);
            ssum += lg[l];
        }
        float inv = 1.f / ssum;
#pragma unroll
        for (int l = 0; l < L_; l++) lr[l] = lg[l] * inv;
    }
    __syncthreads();

    // ---- V projection + attention-weighted context ----
    {
        float ctx[TM];
#pragma unroll
        for (int m = 0; m < TM; m++) ctx[m] = 0.f;
        const float* Wv = Win + (size_t)(2 * D_ + o) * D_;
        for (int l = 0; l < L_; l++) {
            float va[TM];
            gemv<L_ * D_>(sM + l * D_, Wv, va);
#pragma unroll
            for (int m = 0; m < TM; m++) ctx[m] += sAttn[(m * H_ + h) * L_ + l] * va[m];
        }
        float bv = __ldg(bin + 2 * D_ + o);  // softmax sums to 1 -> add bias once
#pragma unroll
        for (int m = 0; m < TM; m++) sX[m * D_ + o] = ctx[m] + bv;
    }
    __syncthreads();

    // ---- out-proj + residual ----
    {
        float ao[TM];
        gemv<D_>(sX, Wout + (size_t)o * D_, ao);
        float bo = __ldg(bout + o);
        __syncthreads();  // all reads of sX(ctx) complete before overwrite
#pragma unroll
        for (int m = 0; m < TM; m++) sX[m * D_ + o] = sE[m * D_ + o] + ao[m] + bo;
    }
    __syncthreads();

    layernorm_inplace(sX, g1, be1, smu, srstd);

    // ---- FFN: fc1 -> relu -> sH (reuse bank smem), fc2 -> residual ----
    float* sH = sM;  // bank no longer needed in smem
    {
        float ha[TM];
        gemv<D_>(sX, W1 + (size_t)o * D_, ha);
        float bb = __ldg(b1 + o);
#pragma unroll
        for (int m = 0; m < TM; m++) sH[m * D_ + o] = fmaxf(ha[m] + bb, 0.f);
    }
    __syncthreads();  // sH visible + all fc1 reads of sX done
    {
        float ea[TM];
        gemv<D_>(sH, W2 + (size_t)o * D_, ea);
        float bb = __ldg(b2 + o);
#pragma unroll
        for (int m = 0; m < TM; m++) sX[m * D_ + o] += ea[m] + bb;  // own column only
    }
    __syncthreads();

    layernorm_inplace(sX, g2, be2, smu, srstd);

    // ---- select: invalid rows keep original embedding ----
#pragma unroll
    for (int m = 0; m < TM; m++)
        if (sValid[m] < 0.5f) sX[m * D_ + o] = sE[m * D_ + o];
    __syncthreads();

    // ---- write new_emb ----
    {
        const float4* sx4 = reinterpret_cast<const float4*>(sX);
        float4* oe = reinterpret_cast<float4*>(out_emb);
        for (int idx = tid; idx < TM * D_ / 4; idx += NT) {
            int m = idx / (D_ / 4);
            if (m < nval) oe[base * (D_ / 4) + idx] = sx4[idx];
        }
    }

    // ---- save projection -> new_bank last row where saved ----
    {
        float sa[TM];
        gemv<D_>(sX, Wsave + (size_t)o * D_, sa);
        float bb = __ldg(bsave + o);
#pragma unroll
        for (int m = 0; m < TM; m++) {
            if (m < nval && sSaved[m] > 0.5f)
                out_bank[(base + m) * (L_ * D_) + (L_ - 1) * D_ + o] = sa[m] + bb;
        }
    }
}

extern "C" void kernel_launch(void* const* d_in, const int* in_sizes, int n_in,
                              void* d_out, int out_size) {
    const float* E = (const float*)d_in[0];
    const float* scores = (const float*)d_in[1];
    const float* bank = (const float*)d_in[2];
    const unsigned int* maskw = (const unsigned int*)d_in[3];
    const float* Wsave = (const float*)d_in[4];
    const float* bsave = (const float*)d_in[5];
    const float* Win = (const float*)d_in[6];
    const float* bin = (const float*)d_in[7];
    const float* Wout = (const float*)d_in[8];
    const float* bout = (const float*)d_in[9];
    const float* W1 = (const float*)d_in[10];
    const float* b1 = (const float*)d_in[11];
    const float* W2 = (const float*)d_in[12];
    const float* b2 = (const float*)d_in[13];
    const float* g1 = (const float*)d_in[14];
    const float* be1 = (const float*)d_in[15];
    const float* g2 = (const float*)d_in[16];
    const float* be2 = (const float*)d_in[17];

    int N = in_sizes[0] / D_;
    float* out = (float*)d_out;
    float* out_emb = out;                               // [N, D]
    float* out_bank = out + (size_t)N * D_;             // [N, L, D]
    float* out_mask = out_bank + (size_t)N * L_ * D_;   // [N, L]

    cudaFuncSetAttribute(mb_kernel, cudaFuncAttributeMaxDynamicSharedMemorySize,
                         SMEM_BYTES);
    int blocks = (N + TM - 1) / TM;
    mb_kernel<<<blocks, NT, SMEM_BYTES>>>(E, scores, bank, maskw, Wsave, bsave, Win,
                                          bin, Wout, bout, W1, b1, W2, b2, g1, be1,
                                          g2, be2, out_emb, out_bank, out_mask, N);
}

// round 4
// speedup vs baseline: 1.4449x; 1.4449x over previous
#include <cuda_runtime.h>
#include <cstdint>

#define D_ 256
#define L_ 4
#define H_ 8
#define TM 32
#define NT 256
#define SXS 264  // padded smem row stride in floats (264*4 % 128 = 32 -> staggers ly groups)

typedef unsigned long long ull;

// ---------------- transposed weights (prologue output) ----------------
// layout: g_WT[mat][k][o], mats: 0=Wq 1=Wk 2=Wv 3=Wout 4=W1 5=W2 6=Wsave
__device__ float g_WT[7 * D_ * D_];

__global__ void transpose_weights_kernel(const float* __restrict__ Win,
                                         const float* __restrict__ Wout,
                                         const float* __restrict__ W1,
                                         const float* __restrict__ W2,
                                         const float* __restrict__ Wsave) {
    int idx = blockIdx.x * blockDim.x + threadIdx.x;
    if (idx >= 7 * D_ * D_) return;
    int mat = idx >> 16;
    int k = (idx >> 8) & 255;
    int o = idx & 255;
    const float* src;
    switch (mat) {
        case 0: src = Win; break;
        case 1: src = Win + D_ * D_; break;
        case 2: src = Win + 2 * D_ * D_; break;
        case 3: src = Wout; break;
        case 4: src = W1; break;
        case 5: src = W2; break;
        default: src = Wsave; break;
    }
    g_WT[idx] = src[o * D_ + k];
}

// ---------------- packed f32x2 helpers (sm_103a) ----------------
__device__ __forceinline__ ull fma2(ull a, ull b, ull c) {
    ull r;
    asm("fma.rn.f32x2 %0, %1, %2, %3;" : "=l"(r) : "l"(a), "l"(b), "l"(c));
    return r;
}
__device__ __forceinline__ ull pk(float lo, float hi) {
    ull r;
    asm("mov.b64 %0, {%1,%2};" : "=l"(r) : "f"(lo), "f"(hi));
    return r;
}
__device__ __forceinline__ float f2sum(ull v) {
    float lo, hi;
    asm("mov.b64 {%0,%1}, %2;" : "=f"(lo), "=f"(hi) : "l"(v));
    return lo + hi;
}
__device__ __forceinline__ float wred(float v) {
#pragma unroll
    for (int s = 16; s > 0; s >>= 1) v += __shfl_xor_sync(0xffffffffu, v, s);
    return v;
}

// ---------------- register-tiled GEMV: 8 rows x 4 cols per thread ----------------
// A: tile base (row 0 of this CTA's 32-row tile), row stride ldA floats.
// WT: transposed weight [k][o]. out[i][j] = sum_k A[ly*8+i][k] * WT[k][col0+j].
__device__ __forceinline__ void gemv84(const float* __restrict__ A, int ldA,
                                       const float* __restrict__ WT, int col0,
                                       int ly, float out[8][4]) {
    ull acc[8][4];
#pragma unroll
    for (int i = 0; i < 8; i++)
#pragma unroll
        for (int j = 0; j < 4; j++) acc[i][j] = 0ull;
    const float* Arow = A + (size_t)(ly * 8) * ldA;
#pragma unroll 1
    for (int kc = 0; kc < D_; kc += 4) {
        // one 128B line per warp per load (cols contiguous via transposed weights)
        float4 w0 = __ldg(reinterpret_cast<const float4*>(WT + (kc + 0) * D_ + col0));
        float4 w1 = __ldg(reinterpret_cast<const float4*>(WT + (kc + 1) * D_ + col0));
        float4 w2 = __ldg(reinterpret_cast<const float4*>(WT + (kc + 2) * D_ + col0));
        float4 w3 = __ldg(reinterpret_cast<const float4*>(WT + (kc + 3) * D_ + col0));
        ull wp0[4] = {pk(w0.x, w1.x), pk(w0.y, w1.y), pk(w0.z, w1.z), pk(w0.w, w1.w)};
        ull wp1[4] = {pk(w2.x, w3.x), pk(w2.y, w3.y), pk(w2.z, w3.z), pk(w2.w, w3.w)};
#pragma unroll
        for (int i = 0; i < 8; i++) {
            float4 a = *reinterpret_cast<const float4*>(Arow + i * ldA + kc);
            ull a01 = pk(a.x, a.y), a23 = pk(a.z, a.w);
#pragma unroll
            for (int j = 0; j < 4; j++) {
                acc[i][j] = fma2(a01, wp0[j], acc[i][j]);
                acc[i][j] = fma2(a23, wp1[j], acc[i][j]);
            }
        }
    }
#pragma unroll
    for (int i = 0; i < 8; i++)
#pragma unroll
        for (int j = 0; j < 4; j++) out[i][j] = f2sum(acc[i][j]);
}

__device__ __forceinline__ void layernorm_inplace(float* sX, const float* __restrict__ g,
                                                  const float* __restrict__ b,
                                                  float* smu, float* srstd) {
    const int w = threadIdx.x >> 5, lane = threadIdx.x & 31;
#pragma unroll
    for (int k = 0; k < TM / 8; k++) {
        int m = w * (TM / 8) + k;
        float s = 0.f, s2 = 0.f;
#pragma unroll
        for (int i = lane; i < D_; i += 32) {
            float v = sX[m * SXS + i];
            s += v;
            s2 += v * v;
        }
        s = wred(s);
        s2 = wred(s2);
        if (lane == 0) {
            float mu = s * (1.f / D_);
            float var = s2 * (1.f / D_) - mu * mu;
            smu[m] = mu;
            srstd[m] = rsqrtf(var + 1e-5f);
        }
    }
    __syncthreads();
    const int o = threadIdx.x;
    float gg = __ldg(g + o), bb = __ldg(b + o);
#pragma unroll
    for (int m = 0; m < TM; m++)
        sX[m * SXS + o] = (sX[m * SXS + o] - smu[m]) * srstd[m] * gg + bb;
    __syncthreads();
}

constexpr int SMEM_FLOATS = 2 * TM * SXS   // sX, sB1 (sQ/sCtx/sH alias)
                            + TM * H_ * L_ // sAttn
                            + TM + TM      // smu, srstd
                            + TM + TM      // sValid, sSaved
                            + TM * L_;     // sKpm
constexpr int SMEM_BYTES = SMEM_FLOATS * 4;

__global__ void __launch_bounds__(NT, 2)
mb_kernel(const float* __restrict__ E, const float* __restrict__ scores,
          const float* __restrict__ bank, const unsigned int* __restrict__ maskw,
          const float* __restrict__ bsave, const float* __restrict__ bin,
          const float* __restrict__ bout, const float* __restrict__ b1,
          const float* __restrict__ b2, const float* __restrict__ g1,
          const float* __restrict__ be1, const float* __restrict__ g2,
          const float* __restrict__ be2, float* __restrict__ out_emb,
          float* __restrict__ out_bank, float* __restrict__ out_mask, int N) {
    extern __shared__ float sm[];
    float* sX = sm;                 // [TM][SXS]
    float* sB1 = sX + TM * SXS;     // [TM][SXS]  (aliases sQ / sCtx / sH)
    float* sAttn = sB1 + TM * SXS;  // [TM][H][L]
    float* smu = sAttn + TM * H_ * L_;
    float* srstd = smu + TM;
    float* sValid = srstd + TM;
    float* sSaved = sValid + TM;
    float* sKpm = sSaved + TM;      // [TM][L]

    const int tid = threadIdx.x;
    const int w = tid >> 5;          // warp == head == 32-col group
    const int lane = tid & 31;
    const int lx = lane & 7;         // col sub-group
    const int ly = lane >> 3;        // row group
    const int col0 = w * 32 + lx * 4;
    const long base = (long)blockIdx.x * TM;  // N % TM == 0 for this problem

    const float* WQt = g_WT;
    const float* WKt = g_WT + 1 * D_ * D_;
    const float* WVt = g_WT + 2 * D_ * D_;
    const float* WOt = g_WT + 3 * D_ * D_;
    const float* W1t = g_WT + 4 * D_ * D_;
    const float* W2t = g_WT + 5 * D_ * D_;
    const float* WSt = g_WT + 6 * D_ * D_;

    // ---- flags + new_mask output ----
    if (tid < TM) {
        int m = tid;
        long g = base + m;
        float sc = scores[g];
        float sv = (sc > 0.f) ? 1.f : 0.f;
        unsigned int mw[L_];
#pragma unroll
        for (int l = 0; l < L_; l++) mw[l] = maskw[g * L_ + l];
        float valid = (mw[L_ - 1] == 0u) ? 1.f : 0.f;
        sSaved[m] = sv;
        sValid[m] = valid;
#pragma unroll
        for (int l = 0; l < L_; l++)
            sKpm[m * L_ + l] = (valid > 0.5f && mw[l] != 0u) ? 1.f : 0.f;
#pragma unroll
        for (int l = 0; l < L_; l++) {
            float om;
            if (sv > 0.5f)
                om = (l < L_ - 1) ? ((mw[l + 1] != 0u) ? 1.f : 0.f) : 0.f;
            else
                om = (mw[l] != 0u) ? 1.f : 0.f;
            out_mask[g * L_ + l] = om;
        }
    }
    __syncthreads();

    // ---- bank copy-out (all rows except the save-row), also warms L1 for K/V ----
    {
        const float4* gb = reinterpret_cast<const float4*>(bank) + base * (L_ * D_ / 4);
        float4* ob = reinterpret_cast<float4*>(out_bank) + base * (L_ * D_ / 4);
        for (int idx = tid; idx < TM * L_ * D_ / 4; idx += NT) {
            int m = idx >> 8;             // L*D/4 = 256 float4 per track
            int rem = idx & 255;
            int r = rem >> 6;             // D/4 = 64
            bool sv = sSaved[m] > 0.5f;
            float4 v;
            if (sv) {
                if (r == L_ - 1) continue;  // written at the end (save_embed)
                v = __ldg(gb + idx + (D_ / 4));
            } else {
                v = __ldg(gb + idx);
            }
            ob[idx] = v;
        }
    }

    // ---- Q projection -> sQ (alias sB1), biased ----
    float* sQ = sB1;
    {
        float q[8][4];
        gemv84(E + base * D_, D_, WQt, col0, ly, q);
        float4 bq = *reinterpret_cast<const float4*>(bin + col0);
#pragma unroll
        for (int i = 0; i < 8; i++) {
            float4 v = make_float4(q[i][0] + bq.x, q[i][1] + bq.y, q[i][2] + bq.z,
                                   q[i][3] + bq.w);
            *reinterpret_cast<float4*>(sQ + (ly * 8 + i) * SXS + col0) = v;
        }
    }
    // own-thread smem round trip: no sync needed

    // ---- K projections + logits (warp w == head w since HD=32) ----
    {
        float4 bk = *reinterpret_cast<const float4*>(bin + D_ + col0);
        for (int l = 0; l < L_; l++) {
            float kk[8][4];
            gemv84(bank + (base * L_ + l) * D_, L_ * D_, WKt, col0, ly, kk);
#pragma unroll
            for (int i = 0; i < 8; i++) {
                int row = ly * 8 + i;
                float4 qi = *reinterpret_cast<const float4*>(sQ + row * SXS + col0);
                float p = (kk[i][0] + bk.x) * qi.x + (kk[i][1] + bk.y) * qi.y +
                          (kk[i][2] + bk.z) * qi.z + (kk[i][3] + bk.w) * qi.w;
                p += __shfl_xor_sync(0xffffffffu, p, 1);
                p += __shfl_xor_sync(0xffffffffu, p, 2);
                p += __shfl_xor_sync(0xffffffffu, p, 4);
                if (lx == 0) sAttn[(row * H_ + w) * L_ + l] = p;
            }
        }
    }
    __syncthreads();

    // ---- masked softmax over L (one thread per (m,h)) ----
    {
        int m = tid >> 3, hh = tid & 7;
        float* lr = &sAttn[(m * H_ + hh) * L_];
        float lg[L_];
#pragma unroll
        for (int l = 0; l < L_; l++) {
            float v = lr[l] * 0.17677669529663687f;  // 1/sqrt(32)
            if (sKpm[m * L_ + l] > 0.5f) v = -1e9f;
            lg[l] = v;
        }
        float mx = fmaxf(fmaxf(lg[0], lg[1]), fmaxf(lg[2], lg[3]));
        float ssum = 0.f;
#pragma unroll
        for (int l = 0; l < L_; l++) {
            lg[l] = expf(lg[l] - mx);
            ssum += lg[l];
        }
        float inv = 1.f / ssum;
#pragma unroll
        for (int l = 0; l < L_; l++) lr[l] = lg[l] * inv;
    }
    __syncthreads();

    // ---- V projections + attention-weighted context -> sCtx (alias sB1) ----
    float* sCtx = sB1;  // sQ dead after logits
    {
        float4 bv = *reinterpret_cast<const float4*>(bin + 2 * D_ + col0);
        for (int l = 0; l < L_; l++) {
            float vv[8][4];
            gemv84(bank + (base * L_ + l) * D_, L_ * D_, WVt, col0, ly, vv);
#pragma unroll
            for (int i = 0; i < 8; i++) {
                int row = ly * 8 + i;
                float at = sAttn[(row * H_ + w) * L_ + l];
                float4 prev;
                if (l == 0)
                    prev = make_float4(0.f, 0.f, 0.f, 0.f);
                else
                    prev = *reinterpret_cast<const float4*>(sCtx + row * SXS + col0);
                float4 v = make_float4(prev.x + at * vv[i][0], prev.y + at * vv[i][1],
                                       prev.z + at * vv[i][2], prev.w + at * vv[i][3]);
                if (l == L_ - 1) {  // softmax sums to 1 -> add V bias once
                    v.x += bv.x; v.y += bv.y; v.z += bv.z; v.w += bv.w;
                }
                *reinterpret_cast<float4*>(sCtx + row * SXS + col0) = v;
            }
        }
    }
    __syncthreads();

    // ---- out-proj + residual -> sX ----
    {
        float ao[8][4];
        gemv84(sCtx, SXS, WOt, col0, ly, ao);
        float4 bo = *reinterpret_cast<const float4*>(bout + col0);
#pragma unroll
        for (int i = 0; i < 8; i++) {
            int row = ly * 8 + i;
            float4 e = __ldg(reinterpret_cast<const float4*>(E + (base + row) * D_ + col0));
            float4 v = make_float4(ao[i][0] + bo.x + e.x, ao[i][1] + bo.y + e.y,
                                   ao[i][2] + bo.z + e.z, ao[i][3] + bo.w + e.w);
            *reinterpret_cast<float4*>(sX + row * SXS + col0) = v;
        }
    }
    __syncthreads();

    layernorm_inplace(sX, g1, be1, smu, srstd);

    // ---- FFN: fc1 -> relu -> sH (alias sB1); fc2 -> residual into sX ----
    float* sH = sB1;
    {
        float ha[8][4];
        gemv84(sX, SXS, W1t, col0, ly, ha);
        float4 bb = *reinterpret_cast<const float4*>(b1 + col0);
#pragma unroll
        for (int i = 0; i < 8; i++) {
            int row = ly * 8 + i;
            float4 v = make_float4(fmaxf(ha[i][0] + bb.x, 0.f), fmaxf(ha[i][1] + bb.y, 0.f),
                                   fmaxf(ha[i][2] + bb.z, 0.f), fmaxf(ha[i][3] + bb.w, 0.f));
            *reinterpret_cast<float4*>(sH + row * SXS + col0) = v;
        }
    }
    __syncthreads();
    {
        float ea[8][4];
        gemv84(sH, SXS, W2t, col0, ly, ea);
        float4 bb = *reinterpret_cast<const float4*>(b2 + col0);
#pragma unroll
        for (int i = 0; i < 8; i++) {
            int row = ly * 8 + i;
            float4 prev = *reinterpret_cast<const float4*>(sX + row * SXS + col0);
            float4 v = make_float4(prev.x + ea[i][0] + bb.x, prev.y + ea[i][1] + bb.y,
                                   prev.z + ea[i][2] + bb.z, prev.w + ea[i][3] + bb.w);
            *reinterpret_cast<float4*>(sX + row * SXS + col0) = v;
        }
    }
    __syncthreads();

    layernorm_inplace(sX, g2, be2, smu, srstd);

    // ---- select: invalid rows keep original embedding (col-mapped) ----
    {
        const int o = tid;
#pragma unroll
        for (int m = 0; m < TM; m++)
            if (sValid[m] < 0.5f) sX[m * SXS + o] = __ldg(E + (base + m) * D_ + o);
    }
    __syncthreads();

    // ---- write new_emb ----
    {
        float4* oe = reinterpret_cast<float4*>(out_emb) + base * (D_ / 4);
        for (int idx = tid; idx < TM * D_ / 4; idx += NT) {
            int m = idx >> 6, c = idx & 63;
            oe[idx] = *reinterpret_cast<const float4*>(sX + m * SXS + c * 4);
        }
    }

    // ---- save projection -> new_bank last row where saved ----
    {
        float sa[8][4];
        gemv84(sX, SXS, WSt, col0, ly, sa);
        float4 bb = *reinterpret_cast<const float4*>(bsave + col0);
#pragma unroll
        for (int i = 0; i < 8; i++) {
            int row = ly * 8 + i;
            if (sSaved[row] > 0.5f) {
                float4 v = make_float4(sa[i][0] + bb.x, sa[i][1] + bb.y, sa[i][2] + bb.z,
                                       sa[i][3] + bb.w);
                *reinterpret_cast<float4*>(out_bank + (base + row) * (L_ * D_) +
                                           (L_ - 1) * D_ + col0) = v;
            }
        }
    }
}

extern "C" void kernel_launch(void* const* d_in, const int* in_sizes, int n_in,
                              void* d_out, int out_size) {
    const float* E = (const float*)d_in[0];
    const float* scores = (const float*)d_in[1];
    const float* bank = (const float*)d_in[2];
    const unsigned int* maskw = (const unsigned int*)d_in[3];
    const float* Wsave = (const float*)d_in[4];
    const float* bsave = (const float*)d_in[5];
    const float* Win = (const float*)d_in[6];
    const float* bin = (const float*)d_in[7];
    const float* Wout = (const float*)d_in[8];
    const float* bout = (const float*)d_in[9];
    const float* W1 = (const float*)d_in[10];
    const float* b1 = (const float*)d_in[11];
    const float* W2 = (const float*)d_in[12];
    const float* b2 = (const float*)d_in[13];
    const float* g1 = (const float*)d_in[14];
    const float* be1 = (const float*)d_in[15];
    const float* g2 = (const float*)d_in[16];
    const float* be2 = (const float*)d_in[17];

    int N = in_sizes[0] / D_;
    float* out = (float*)d_out;
    float* out_emb = out;                              // [N, D]
    float* out_bank = out + (size_t)N * D_;            // [N, L, D]
    float* out_mask = out_bank + (size_t)N * L_ * D_;  // [N, L]

    transpose_weights_kernel<<<(7 * D_ * D_ + 255) / 256, 256>>>(Win, Wout, W1, W2,
                                                                 Wsave);

    cudaFuncSetAttribute(mb_kernel, cudaFuncAttributeMaxDynamicSharedMemorySize,
                         SMEM_BYTES);
    int blocks = N / TM;  // N % TM == 0 for this dataset (100000 = 3125*32)
    mb_kernel<<<blocks, NT, SMEM_BYTES>>>(E, scores, bank, maskw, bsave, bin, bout, b1,
                                          b2, g1, be1, g2, be2, out_emb, out_bank,
                                          out_mask, N);
}

// round 5
// speedup vs baseline: 2.0077x; 1.3894x over previous
#include <cuda_runtime.h>
#include <cstdint>

#define D_ 256
#define L_ 4
#define H_ 8
#define TM 32
#define NT 256
#define SXS 264  // padded smem row stride in floats

typedef unsigned long long ull;

// ---------------- interleaved-pair transposed weights ----------------
// g_WT2[mat][kp][o] is a 64-bit element = (W[2kp][o], W[2kp+1][o]),
// mats: 0=Wq 1=Wk 2=Wv 3=Wout 4=W1 5=W2 6=Wsave
__device__ ull g_WT2[7 * (D_ / 2) * D_];

__global__ void pack_weights_kernel(const float* __restrict__ Win,
                                    const float* __restrict__ Wout,
                                    const float* __restrict__ W1,
                                    const float* __restrict__ W2,
                                    const float* __restrict__ Wsave) {
    int idx = blockIdx.x * blockDim.x + threadIdx.x;
    if (idx >= 7 * (D_ / 2) * D_) return;
    int mat = idx / ((D_ / 2) * D_);
    int rem = idx - mat * ((D_ / 2) * D_);
    int kp = rem >> 8;
    int o = rem & 255;
    const float* src;
    switch (mat) {
        case 0: src = Win; break;
        case 1: src = Win + D_ * D_; break;
        case 2: src = Win + 2 * D_ * D_; break;
        case 3: src = Wout; break;
        case 4: src = W1; break;
        case 5: src = W2; break;
        default: src = Wsave; break;
    }
    float lo = src[o * D_ + 2 * kp];
    float hi = src[o * D_ + 2 * kp + 1];
    *reinterpret_cast<float2*>(&g_WT2[idx]) = make_float2(lo, hi);
}

// ---------------- packed f32x2 helpers (sm_103a) ----------------
__device__ __forceinline__ ull fma2(ull a, ull b, ull c) {
    ull r;
    asm("fma.rn.f32x2 %0, %1, %2, %3;" : "=l"(r) : "l"(a), "l"(b), "l"(c));
    return r;
}
__device__ __forceinline__ float f2sum(ull v) {
    float lo, hi;
    asm("mov.b64 {%0,%1}, %2;" : "=f"(lo), "=f"(hi) : "l"(v));
    return lo + hi;
}
__device__ __forceinline__ float wred(float v) {
#pragma unroll
    for (int s = 16; s > 0; s >>= 1) v += __shfl_xor_sync(0xffffffffu, v, s);
    return v;
}

// ---------------- register-tiled GEMV: 8 rows x 4 cols per thread ----------------
// A: tile base, row stride ldA floats (16B-aligned rows).
// WT2: interleaved-pair weights for this matrix.
// out[i][j] = sum_k A[ly*8+i][k] * W[k][col0+j].
// Inner loop: 4 LDG.128 + 8 LDS.128 + 64 FFMA2, zero packing ops.
__device__ __forceinline__ void gemv84(const float* __restrict__ A, int ldA,
                                       const ull* __restrict__ WT2, int col0,
                                       int ly, float out[8][4]) {
    ull acc[8][4];
#pragma unroll
    for (int i = 0; i < 8; i++)
#pragma unroll
        for (int j = 0; j < 4; j++) acc[i][j] = 0ull;
    const float* Arow = A + (size_t)(ly * 8) * ldA;
#pragma unroll 1
    for (int kc = 0; kc < D_; kc += 4) {
        const ull* Wp = WT2 + (size_t)(kc >> 1) * D_ + col0;
        ulonglong2 wA = __ldg(reinterpret_cast<const ulonglong2*>(Wp));
        ulonglong2 wB = __ldg(reinterpret_cast<const ulonglong2*>(Wp + 2));
        ulonglong2 wC = __ldg(reinterpret_cast<const ulonglong2*>(Wp + D_));
        ulonglong2 wD = __ldg(reinterpret_cast<const ulonglong2*>(Wp + D_ + 2));
        ull wp0[4] = {wA.x, wA.y, wB.x, wB.y};  // (k,k+1) for cols 0..3
        ull wp1[4] = {wC.x, wC.y, wD.x, wD.y};  // (k+2,k+3) for cols 0..3
#pragma unroll
        for (int i = 0; i < 8; i++) {
            ulonglong2 av =
                *reinterpret_cast<const ulonglong2*>(Arow + i * ldA + kc);
#pragma unroll
            for (int j = 0; j < 4; j++) {
                acc[i][j] = fma2(av.x, wp0[j], acc[i][j]);
                acc[i][j] = fma2(av.y, wp1[j], acc[i][j]);
            }
        }
    }
#pragma unroll
    for (int i = 0; i < 8; i++)
#pragma unroll
        for (int j = 0; j < 4; j++) out[i][j] = f2sum(acc[i][j]);
}

__device__ __forceinline__ void layernorm_inplace(float* sX, const float* __restrict__ g,
                                                  const float* __restrict__ b,
                                                  float* smu, float* srstd) {
    const int w = threadIdx.x >> 5, lane = threadIdx.x & 31;
#pragma unroll
    for (int k = 0; k < TM / 8; k++) {
        int m = w * (TM / 8) + k;
        float s = 0.f, s2 = 0.f;
#pragma unroll
        for (int i = lane; i < D_; i += 32) {
            float v = sX[m * SXS + i];
            s += v;
            s2 += v * v;
        }
        s = wred(s);
        s2 = wred(s2);
        if (lane == 0) {
            float mu = s * (1.f / D_);
            float var = s2 * (1.f / D_) - mu * mu;
            smu[m] = mu;
            srstd[m] = rsqrtf(var + 1e-5f);
        }
    }
    __syncthreads();
    const int o = threadIdx.x;
    float gg = __ldg(g + o), bb = __ldg(b + o);
#pragma unroll
    for (int m = 0; m < TM; m++)
        sX[m * SXS + o] = (sX[m * SXS + o] - smu[m]) * srstd[m] * gg + bb;
    __syncthreads();
}

constexpr int SMEM_FLOATS = 2 * TM * SXS   // sX, sB1 (sQ/sCtx/sH alias)
                            + TM * H_ * L_ // sAttn
                            + TM + TM      // smu, srstd
                            + TM + TM      // sValid, sSaved
                            + TM * L_;     // sKpm
constexpr int SMEM_BYTES = SMEM_FLOATS * 4;

__global__ void __launch_bounds__(NT, 2)
mb_kernel(const float* __restrict__ E, const float* __restrict__ scores,
          const float* __restrict__ bank, const unsigned int* __restrict__ maskw,
          const float* __restrict__ bsave, const float* __restrict__ bin,
          const float* __restrict__ bout, const float* __restrict__ b1,
          const float* __restrict__ b2, const float* __restrict__ g1,
          const float* __restrict__ be1, const float* __restrict__ g2,
          const float* __restrict__ be2, float* __restrict__ out_emb,
          float* __restrict__ out_bank, float* __restrict__ out_mask, int N) {
    extern __shared__ float sm[];
    float* sX = sm;                 // [TM][SXS]
    float* sB1 = sX + TM * SXS;     // [TM][SXS]  (aliases sQ / sCtx / sH)
    float* sAttn = sB1 + TM * SXS;  // [TM][H][L]
    float* smu = sAttn + TM * H_ * L_;
    float* srstd = smu + TM;
    float* sValid = srstd + TM;
    float* sSaved = sValid + TM;
    float* sKpm = sSaved + TM;      // [TM][L]

    const int tid = threadIdx.x;
    const int w = tid >> 5;          // warp == head == 32-col group
    const int lane = tid & 31;
    const int lx = lane & 7;         // col sub-group
    const int ly = lane >> 3;        // row group
    const int col0 = w * 32 + lx * 4;
    const long base = (long)blockIdx.x * TM;  // N % TM == 0 for this dataset

    const ull* WQt = g_WT2;
    const ull* WKt = g_WT2 + 1 * (D_ / 2) * D_;
    const ull* WVt = g_WT2 + 2 * (D_ / 2) * D_;
    const ull* WOt = g_WT2 + 3 * (D_ / 2) * D_;
    const ull* W1t = g_WT2 + 4 * (D_ / 2) * D_;
    const ull* W2t = g_WT2 + 5 * (D_ / 2) * D_;
    const ull* WSt = g_WT2 + 6 * (D_ / 2) * D_;

    // ---- flags + new_mask output ----
    if (tid < TM) {
        int m = tid;
        long g = base + m;
        float sc = scores[g];
        float sv = (sc > 0.f) ? 1.f : 0.f;
        unsigned int mw[L_];
#pragma unroll
        for (int l = 0; l < L_; l++) mw[l] = maskw[g * L_ + l];
        float valid = (mw[L_ - 1] == 0u) ? 1.f : 0.f;
        sSaved[m] = sv;
        sValid[m] = valid;
#pragma unroll
        for (int l = 0; l < L_; l++)
            sKpm[m * L_ + l] = (valid > 0.5f && mw[l] != 0u) ? 1.f : 0.f;
#pragma unroll
        for (int l = 0; l < L_; l++) {
            float om;
            if (sv > 0.5f)
                om = (l < L_ - 1) ? ((mw[l + 1] != 0u) ? 1.f : 0.f) : 0.f;
            else
                om = (mw[l] != 0u) ? 1.f : 0.f;
            out_mask[g * L_ + l] = om;
        }
    }
    __syncthreads();

    // ---- bank copy-out (all rows except the save-row), also warms L1 for K/V ----
    {
        const float4* gb = reinterpret_cast<const float4*>(bank) + base * (L_ * D_ / 4);
        float4* ob = reinterpret_cast<float4*>(out_bank) + base * (L_ * D_ / 4);
        for (int idx = tid; idx < TM * L_ * D_ / 4; idx += NT) {
            int m = idx >> 8;             // L*D/4 = 256 float4 per track
            int rem = idx & 255;
            int r = rem >> 6;             // D/4 = 64
            bool sv = sSaved[m] > 0.5f;
            float4 v;
            if (sv) {
                if (r == L_ - 1) continue;  // written at the end (save_embed)
                v = __ldg(gb + idx + (D_ / 4));
            } else {
                v = __ldg(gb + idx);
            }
            ob[idx] = v;
        }
    }

    // ---- Q projection -> sQ (alias sB1), biased ----
    float* sQ = sB1;
    {
        float q[8][4];
        gemv84(E + base * D_, D_, WQt, col0, ly, q);
        float4 bq = *reinterpret_cast<const float4*>(bin + col0);
#pragma unroll
        for (int i = 0; i < 8; i++) {
            float4 v = make_float4(q[i][0] + bq.x, q[i][1] + bq.y, q[i][2] + bq.z,
                                   q[i][3] + bq.w);
            *reinterpret_cast<float4*>(sQ + (ly * 8 + i) * SXS + col0) = v;
        }
    }
    // own-thread smem round trip: no sync needed

    // ---- K projections + logits (warp w == head w since HD=32) ----
    {
        float4 bk = *reinterpret_cast<const float4*>(bin + D_ + col0);
        for (int l = 0; l < L_; l++) {
            float kk[8][4];
            gemv84(bank + (base * L_ + l) * D_, L_ * D_, WKt, col0, ly, kk);
#pragma unroll
            for (int i = 0; i < 8; i++) {
                int row = ly * 8 + i;
                float4 qi = *reinterpret_cast<const float4*>(sQ + row * SXS + col0);
                float p = (kk[i][0] + bk.x) * qi.x + (kk[i][1] + bk.y) * qi.y +
                          (kk[i][2] + bk.z) * qi.z + (kk[i][3] + bk.w) * qi.w;
                p += __shfl_xor_sync(0xffffffffu, p, 1);
                p += __shfl_xor_sync(0xffffffffu, p, 2);
                p += __shfl_xor_sync(0xffffffffu, p, 4);
                if (lx == 0) sAttn[(row * H_ + w) * L_ + l] = p;
            }
        }
    }
    __syncthreads();

    // ---- masked softmax over L (one thread per (m,h)) ----
    {
        int m = tid >> 3, hh = tid & 7;
        float* lr = &sAttn[(m * H_ + hh) * L_];
        float lg[L_];
#pragma unroll
        for (int l = 0; l < L_; l++) {
            float v = lr[l] * 0.17677669529663687f;  // 1/sqrt(32)
            if (sKpm[m * L_ + l] > 0.5f) v = -1e9f;
            lg[l] = v;
        }
        float mx = fmaxf(fmaxf(lg[0], lg[1]), fmaxf(lg[2], lg[3]));
        float ssum = 0.f;
#pragma unroll
        for (int l = 0; l < L_; l++) {
            lg[l] = expf(lg[l] - mx);
            ssum += lg[l];
        }
        float inv = 1.f / ssum;
#pragma unroll
        for (int l = 0; l < L_; l++) lr[l] = lg[l] * inv;
    }
    __syncthreads();

    // ---- V projections + attention-weighted context -> sCtx (alias sB1) ----
    float* sCtx = sB1;  // sQ dead after logits
    {
        float4 bv = *reinterpret_cast<const float4*>(bin + 2 * D_ + col0);
        for (int l = 0; l < L_; l++) {
            float vv[8][4];
            gemv84(bank + (base * L_ + l) * D_, L_ * D_, WVt, col0, ly, vv);
#pragma unroll
            for (int i = 0; i < 8; i++) {
                int row = ly * 8 + i;
                float at = sAttn[(row * H_ + w) * L_ + l];
                float4 prev;
                if (l == 0)
                    prev = make_float4(0.f, 0.f, 0.f, 0.f);
                else
                    prev = *reinterpret_cast<const float4*>(sCtx + row * SXS + col0);
                float4 v = make_float4(prev.x + at * vv[i][0], prev.y + at * vv[i][1],
                                       prev.z + at * vv[i][2], prev.w + at * vv[i][3]);
                if (l == L_ - 1) {  // softmax sums to 1 -> add V bias once
                    v.x += bv.x; v.y += bv.y; v.z += bv.z; v.w += bv.w;
                }
                *reinterpret_cast<float4*>(sCtx + row * SXS + col0) = v;
            }
        }
    }
    __syncthreads();

    // ---- out-proj + residual -> sX ----
    {
        float ao[8][4];
        gemv84(sCtx, SXS, WOt, col0, ly, ao);
        float4 bo = *reinterpret_cast<const float4*>(bout + col0);
#pragma unroll
        for (int i = 0; i < 8; i++) {
            int row = ly * 8 + i;
            float4 e = __ldg(reinterpret_cast<const float4*>(E + (base + row) * D_ + col0));
            float4 v = make_float4(ao[i][0] + bo.x + e.x, ao[i][1] + bo.y + e.y,
                                   ao[i][2] + bo.z + e.z, ao[i][3] + bo.w + e.w);
            *reinterpret_cast<float4*>(sX + row * SXS + col0) = v;
        }
    }
    __syncthreads();

    layernorm_inplace(sX, g1, be1, smu, srstd);

    // ---- FFN: fc1 -> relu -> sH (alias sB1); fc2 -> residual into sX ----
    float* sH = sB1;
    {
        float ha[8][4];
        gemv84(sX, SXS, W1t, col0, ly, ha);
        float4 bb = *reinterpret_cast<const float4*>(b1 + col0);
#pragma unroll
        for (int i = 0; i < 8; i++) {
            int row = ly * 8 + i;
            float4 v = make_float4(fmaxf(ha[i][0] + bb.x, 0.f), fmaxf(ha[i][1] + bb.y, 0.f),
                                   fmaxf(ha[i][2] + bb.z, 0.f), fmaxf(ha[i][3] + bb.w, 0.f));
            *reinterpret_cast<float4*>(sH + row * SXS + col0) = v;
        }
    }
    __syncthreads();
    {
        float ea[8][4];
        gemv84(sH, SXS, W2t, col0, ly, ea);
        float4 bb = *reinterpret_cast<const float4*>(b2 + col0);
#pragma unroll
        for (int i = 0; i < 8; i++) {
            int row = ly * 8 + i;
            float4 prev = *reinterpret_cast<const float4*>(sX + row * SXS + col0);
            float4 v = make_float4(prev.x + ea[i][0] + bb.x, prev.y + ea[i][1] + bb.y,
                                   prev.z + ea[i][2] + bb.z, prev.w + ea[i][3] + bb.w);
            *reinterpret_cast<float4*>(sX + row * SXS + col0) = v;
        }
    }
    __syncthreads();

    layernorm_inplace(sX, g2, be2, smu, srstd);

    // ---- select: invalid rows keep original embedding (col-mapped) ----
    {
        const int o = tid;
#pragma unroll
        for (int m = 0; m < TM; m++)
            if (sValid[m] < 0.5f) sX[m * SXS + o] = __ldg(E + (base + m) * D_ + o);
    }
    __syncthreads();

    // ---- write new_emb ----
    {
        float4* oe = reinterpret_cast<float4*>(out_emb) + base * (D_ / 4);
        for (int idx = tid; idx < TM * D_ / 4; idx += NT) {
            int m = idx >> 6, c = idx & 63;
            oe[idx] = *reinterpret_cast<const float4*>(sX + m * SXS + c * 4);
        }
    }

    // ---- save projection -> new_bank last row where saved ----
    {
        float sa[8][4];
        gemv84(sX, SXS, WSt, col0, ly, sa);
        float4 bb = *reinterpret_cast<const float4*>(bsave + col0);
#pragma unroll
        for (int i = 0; i < 8; i++) {
            int row = ly * 8 + i;
            if (sSaved[row] > 0.5f) {
                float4 v = make_float4(sa[i][0] + bb.x, sa[i][1] + bb.y, sa[i][2] + bb.z,
                                       sa[i][3] + bb.w);
                *reinterpret_cast<float4*>(out_bank + (base + row) * (L_ * D_) +
                                           (L_ - 1) * D_ + col0) = v;
            }
        }
    }
}

extern "C" void kernel_launch(void* const* d_in, const int* in_sizes, int n_in,
                              void* d_out, int out_size) {
    const float* E = (const float*)d_in[0];
    const float* scores = (const float*)d_in[1];
    const float* bank = (const float*)d_in[2];
    const unsigned int* maskw = (const unsigned int*)d_in[3];
    const float* Wsave = (const float*)d_in[4];
    const float* bsave = (const float*)d_in[5];
    const float* Win = (const float*)d_in[6];
    const float* bin = (const float*)d_in[7];
    const float* Wout = (const float*)d_in[8];
    const float* bout = (const float*)d_in[9];
    const float* W1 = (const float*)d_in[10];
    const float* b1 = (const float*)d_in[11];
    const float* W2 = (const float*)d_in[12];
    const float* b2 = (const float*)d_in[13];
    const float* g1 = (const float*)d_in[14];
    const float* be1 = (const float*)d_in[15];
    const float* g2 = (const float*)d_in[16];
    const float* be2 = (const float*)d_in[17];

    int N = in_sizes[0] / D_;
    float* out = (float*)d_out;
    float* out_emb = out;                              // [N, D]
    float* out_bank = out + (size_t)N * D_;            // [N, L, D]
    float* out_mask = out_bank + (size_t)N * L_ * D_;  // [N, L]

    pack_weights_kernel<<<(7 * (D_ / 2) * D_ + 255) / 256, 256>>>(Win, Wout, W1, W2,
                                                                  Wsave);

    cudaFuncSetAttribute(mb_kernel, cudaFuncAttributeMaxDynamicSharedMemorySize,
                         SMEM_BYTES);
    int blocks = N / TM;  // N % TM == 0 for this dataset (100000 = 3125*32)
    mb_kernel<<<blocks, NT, SMEM_BYTES>>>(E, scores, bank, maskw, bsave, bin, bout, b1,
                                          b2, g1, be1, g2, be2, out_emb, out_bank,
                                          out_mask, N);
}